// round 12
// baseline (speedup 1.0000x reference)
#include <cuda_runtime.h>
#include <cuda_bf16.h>
#include <cstdint>

// Problem constants: B=256, IN=64, HID=128, OUT=64, T=1000
// Output: ys (B,T,64) then hs (B,T,128), float32.

typedef unsigned long long ull;

// ------------------------- device scratch (no allocs allowed) --------------
__device__ float g_ximp[256 * 64 * 1000];                 // imputed x (B,IN,T)
__device__ float g_pre[131072000];                        // (B,T,[gamH,preZ,preR,preH],128)

// ------------------------- helpers -----------------------------------------
__device__ __forceinline__ void fma2(ull& d, ull a, ull b) {
    asm("fma.rn.f32x2 %0, %1, %2, %0;" : "+l"(d) : "l"(a), "l"(b));
}
__device__ __forceinline__ ull pk2(float lo, float hi) {
    ull r;
    asm("mov.b64 %0, {%1, %2};" : "=l"(r) : "f"(lo), "f"(hi));
    return r;
}
__device__ __forceinline__ float2 up2(ull v) {
    float2 r;
    asm("mov.b64 {%0, %1}, %2;" : "=f"(r.x), "=f"(r.y) : "l"(v));
    return r;
}
__device__ __forceinline__ float sigf(float x) { return 1.f / (1.f + __expf(-x)); }
__device__ __forceinline__ float tanhf_(float x) { return 1.f - 2.f / (1.f + __expf(2.f * x)); }

// ============================================================================
// K1: imputation. One CTA per batch. gamma_x GEMM + LOCF scan + impute.
// ============================================================================
__global__ void __launch_bounds__(256) k1_impute(
    const float* __restrict__ inp, const float* __restrict__ xmean,
    const float* __restrict__ Wdgx, const float* __restrict__ bdgx)
{
    extern __shared__ float sm_[];
    float* sx  = sm_;                 // 64 x 129
    float* smk = sx + 64 * 129;
    float* sd  = smk + 64 * 129;
    float* sg  = sd + 64 * 129;
    float* sW  = sg + 64 * 129;       // 64 x 64
    const int b = blockIdx.x, tid = threadIdx.x;

    for (int e = tid; e < 64 * 64; e += 256) sW[e] = Wdgx[e];
    float xl  = 0.f;
    float xmn = (tid < 64) ? xmean[tid] : 0.f;

    for (int t0 = 0; t0 < 1000; t0 += 128) {
        const int nv = min(128, 1000 - t0);
        __syncthreads();
        for (int e = tid; e < 64 * 128; e += 256) {
            int i = e >> 7, u = e & 127;
            float xv = 0.f, mv = 0.f, dv = 0.f;
            if (u < nv) {
                size_t gb = ((size_t)(b * 3 * 64) + i) * 1000 + t0 + u;
                xv = inp[gb];
                mv = inp[gb + 64 * 1000];
                dv = inp[gb + 2 * 64 * 1000];
            }
            sx[i * 129 + u] = xv; smk[i * 129 + u] = mv; sd[i * 129 + u] = dv;
        }
        __syncthreads();
        for (int e = tid; e < 64 * 128; e += 256) {
            int j = e >> 7, u = e & 127;
            float acc = bdgx[j];
            #pragma unroll 8
            for (int k = 0; k < 64; k++) acc += sd[k * 129 + u] * sW[k * 64 + j];
            sg[j * 129 + u] = __expf(-fmaxf(acc, 0.f));
        }
        __syncthreads();
        if (tid < 64) {
            const int i = tid;
            for (int u = 0; u < nv; u++) {
                float mv = smk[i * 129 + u], xv = sx[i * 129 + u], gv = sg[i * 129 + u];
                if (mv > 0.f) xl = xv;
                sx[i * 129 + u] = mv * xv + (1.f - mv) * (gv * xl + (1.f - gv) * xmn);
            }
        }
        __syncthreads();
        for (int e = tid; e < 64 * 128; e += 256) {
            int i = e >> 7, u = e & 127;
            if (u < nv) g_ximp[((size_t)(b * 64) + i) * 1000 + t0 + u] = sx[i * 129 + u];
        }
    }
}

// ============================================================================
// K2: pre-activations. CTA = (t-tile 64, batch). f32x2 packed over t-pairs.
// ============================================================================
__device__ __forceinline__ void gemm64(const float* __restrict__ s,
                                       const float* __restrict__ sW,
                                       ull acc[16], int h, int base)
{
    #pragma unroll 4
    for (int k = 0; k < 64; k++) {
        float w = sW[k * 128 + h];
        ull w2 = pk2(w, w);
        const ulonglong2* row = (const ulonglong2*)(s + k * 64 + base);
        #pragma unroll
        for (int j = 0; j < 8; j++) {
            ulonglong2 v = row[j];
            fma2(acc[2 * j],     v.x, w2);
            fma2(acc[2 * j + 1], v.y, w2);
        }
    }
}

__device__ __forceinline__ void store_pre(const ull acc[16],
                                          int b, int t0, int base, int h, int c, float bias)
{
    #pragma unroll
    for (int j = 0; j < 16; j++) {
        float2 a = up2(acc[j]);
        int u = base + 2 * j;
        size_t adr = ((size_t)b * 1000 + t0 + u) * 512 + c * 128 + h;
        if (t0 + u < 1000)     g_pre[adr]       = a.x + bias;
        if (t0 + u + 1 < 1000) g_pre[adr + 512] = a.y + bias;
    }
}

__global__ void __launch_bounds__(256) k2_pre(
    const float* __restrict__ inp,
    const float* __restrict__ Wdgh, const float* __restrict__ bdgh,
    const float* __restrict__ Wxz,  const float* __restrict__ Wmz, const float* __restrict__ bmz,
    const float* __restrict__ Wxr,  const float* __restrict__ Wmr,
    const float* __restrict__ Wxh,  const float* __restrict__ Wmh, const float* __restrict__ bmh)
{
    extern __shared__ float sm_[];
    float* sx  = sm_;          // 64k x 64t
    float* sm2 = sx + 4096;
    float* sd  = sm2 + 4096;
    float* sW  = sd + 4096;    // 64 x 128
    const int t0 = blockIdx.x * 64, b = blockIdx.y;
    const int tid = threadIdx.x, h = tid & 127, base = (tid >> 7) * 32;

    for (int e = tid; e < 4096; e += 256) {
        int k = e >> 6, u = e & 63;
        int t = t0 + u;
        float xv = 0.f, mv = 0.f, dv = 0.f;
        if (t < 1000) {
            xv = g_ximp[((size_t)(b * 64) + k) * 1000 + t];
            size_t gb = ((size_t)(b * 3 * 64) + k) * 1000 + t;
            mv = inp[gb + 64 * 1000];
            dv = inp[gb + 2 * 64 * 1000];
        }
        sx[k * 64 + u] = xv; sm2[k * 64 + u] = mv; sd[k * 64 + u] = dv;
    }
    ull acc[16];

    // ---- c0: gammaH ----
    for (int e = tid; e < 8192; e += 256) sW[e] = Wdgh[e];
    __syncthreads();
    #pragma unroll
    for (int j = 0; j < 16; j++) acc[j] = 0ull;
    gemm64(sd, sW, acc, h, base);
    {
        float bb = bdgh[h];
        #pragma unroll
        for (int j = 0; j < 16; j++) {
            float2 a = up2(acc[j]);
            int u = base + 2 * j;
            size_t adr = ((size_t)b * 1000 + t0 + u) * 512 + h;
            if (t0 + u < 1000)     g_pre[adr]       = __expf(-fmaxf(a.x + bb, 0.f));
            if (t0 + u + 1 < 1000) g_pre[adr + 512] = __expf(-fmaxf(a.y + bb, 0.f));
        }
    }
    // ---- c1: preZ ----
    __syncthreads();
    for (int e = tid; e < 8192; e += 256) sW[e] = Wxz[e];
    __syncthreads();
    #pragma unroll
    for (int j = 0; j < 16; j++) acc[j] = 0ull;
    gemm64(sx, sW, acc, h, base);
    __syncthreads();
    for (int e = tid; e < 8192; e += 256) sW[e] = Wmz[e];
    __syncthreads();
    gemm64(sm2, sW, acc, h, base);
    store_pre(acc, b, t0, base, h, 1, bmz[h]);

    // ---- c2: preR ----
    __syncthreads();
    for (int e = tid; e < 8192; e += 256) sW[e] = Wxr[e];
    __syncthreads();
    #pragma unroll
    for (int j = 0; j < 16; j++) acc[j] = 0ull;
    gemm64(sx, sW, acc, h, base);
    __syncthreads();
    for (int e = tid; e < 8192; e += 256) sW[e] = Wmr[e];
    __syncthreads();
    gemm64(sm2, sW, acc, h, base);
    store_pre(acc, b, t0, base, h, 2, 0.f);

    // ---- c3: preH ----
    __syncthreads();
    for (int e = tid; e < 8192; e += 256) sW[e] = Wxh[e];
    __syncthreads();
    #pragma unroll
    for (int j = 0; j < 16; j++) acc[j] = 0ull;
    gemm64(sx, sW, acc, h, base);
    __syncthreads();
    for (int e = tid; e < 8192; e += 256) sW[e] = Wmh[e];
    __syncthreads();
    gemm64(sm2, sW, acc, h, base);
    store_pre(acc, b, t0, base, h, 3, bmh[h]);
}

// ============================================================================
// K3 v3: persistent-register recurrence. 128 CTAs x 512 threads, 2 batches/CTA.
// Thread (tid): pair p = tid>>3 in [0,64), j-chunk c = tid&7 (16 j each).
// Weights: 48 ull = 96 regs/thread (fits 128-reg budget at 512 thr, no spills).
// Reductions through smem (no SHFL). 4 barriers/step.
// Next-step pre-activations prefetched into double-buffered smem by all threads.
// Owner lanes (c<2 -> batch c): 8 per warp, epilogue runs on all 16 warps.
// ============================================================================
__global__ void __launch_bounds__(512, 1) k3_rec(
    const float* __restrict__ Whz, const float* __restrict__ Whr,
    const float* __restrict__ Whh, float* __restrict__ hs)
{
    __shared__ ull shd[2][128];        // gamma-scaled h, duplicated pairs, per batch
    __shared__ ull srhd[2][128];       // r*h, duplicated pairs
    __shared__ ull sredB[4][64][8];    // partials: [z0,z1,r0,r1][pair][chunk]
    __shared__ ull sredC[2][64][8];    // partials: [h0,h1][pair][chunk]
    __shared__ float spre[2][1024];    // double-buffered pre-activations (2 batches x 512)

    const int tid = threadIdx.x;
    const int p  = tid >> 3;           // pair [0,64)
    const int c  = tid & 7;            // chunk [0,8)
    const int jb = c * 16;
    const int bg0 = blockIdx.x * 2;

    // ---- load this thread's weight slice: 16 j x 3 gates, as (W[j][2p],W[j][2p+1])
    ull wz[16], wr[16], wh[16];
    #pragma unroll
    for (int j = 0; j < 16; j++) {
        int row = (jb + j) * 128 + 2 * p;
        wz[j] = *(const ull*)(Whz + row);
        wr[j] = *(const ull*)(Whr + row);
        wh[j] = *(const ull*)(Whh + row);
    }

    // init h = 0
    if (tid < 256) ((ull*)shd)[tid] = 0ull;

    // preload pre(0) into spre[0]
    {
        int b = tid >> 8;                 // 0/1
        int off = (tid & 255) * 2;        // 0..510
        *(ull*)&spre[0][b * 512 + off] =
            *(const ull*)&g_pre[((size_t)(bg0 + b) * 1000) * 512 + off];
    }

    ull h2 = 0ull;                        // gamma-scaled h pair (owner lanes)
    float zx = 0.f, zy = 0.f;
    const bool owner = (c < 2);
    const int b = c;                      // owner's batch (valid when owner)
    const int bg = bg0 + b;
    __syncthreads();

    for (int t = 0; t < 1000; t++) {
        const int par  = t & 1;
        const int parn = par ^ 1;

        // ---- loop-top: prefetch pre(t+1) into spre[parn] (all 512 threads) ----
        {
            int tn = (t + 1 < 1000) ? t + 1 : 999;
            int lb  = tid >> 8;
            int off = (tid & 255) * 2;
            *(ull*)&spre[parn][lb * 512 + off] =
                *(const ull*)&g_pre[((size_t)(bg0 + lb) * 1000 + tn) * 512 + off];
        }

        // ---- stage B: z/r partial dots over this thread's 16-j chunk ----
        ull az0 = 0, az1 = 0, ar0 = 0, ar1 = 0;
        #pragma unroll
        for (int q = 0; q < 8; q++) {
            ulonglong2 h0 = *(const ulonglong2*)&shd[0][jb + 2 * q];
            ulonglong2 h1 = *(const ulonglong2*)&shd[1][jb + 2 * q];
            fma2(az0, h0.x, wz[2 * q]); fma2(az0, h0.y, wz[2 * q + 1]);
            fma2(ar0, h0.x, wr[2 * q]); fma2(ar0, h0.y, wr[2 * q + 1]);
            fma2(az1, h1.x, wz[2 * q]); fma2(az1, h1.y, wz[2 * q + 1]);
            fma2(ar1, h1.x, wr[2 * q]); fma2(ar1, h1.y, wr[2 * q + 1]);
        }
        sredB[0][p][c] = az0; sredB[1][p][c] = az1;
        sredB[2][p][c] = ar0; sredB[3][p][c] = ar1;
        __syncthreads();   // BAR1

        // ---- owner epilogue 1: z, r activations; publish r*h ----
        if (owner) {
            float zsx = 0.f, zsy = 0.f, rsx = 0.f, rsy = 0.f;
            #pragma unroll
            for (int k = 0; k < 4; k++) {
                ulonglong2 vz = *(const ulonglong2*)&sredB[b][p][2 * k];
                ulonglong2 vr = *(const ulonglong2*)&sredB[2 + b][p][2 * k];
                float2 a0 = up2(vz.x), a1 = up2(vz.y);
                float2 b0 = up2(vr.x), b1 = up2(vr.y);
                zsx += a0.x + a1.x; zsy += a0.y + a1.y;
                rsx += b0.x + b1.x; rsy += b0.y + b1.y;
            }
            const float* pp = &spre[par][b * 512];
            float2 zp = *(const float2*)&pp[128 + 2 * p];
            float2 rp = *(const float2*)&pp[256 + 2 * p];
            zx = sigf(zp.x + zsx); zy = sigf(zp.y + zsy);
            float rx = sigf(rp.x + rsx), ry = sigf(rp.y + rsy);
            float2 hv = up2(h2);
            float v0 = rx * hv.x, v1 = ry * hv.y;
            *(float4*)&srhd[b][2 * p] = make_float4(v0, v0, v1, v1);
        }
        __syncthreads();   // BAR2

        // ---- stage C: h_tilde partial dots ----
        ull ah0 = 0, ah1 = 0;
        #pragma unroll
        for (int q = 0; q < 8; q++) {
            ulonglong2 q0 = *(const ulonglong2*)&srhd[0][jb + 2 * q];
            ulonglong2 q1 = *(const ulonglong2*)&srhd[1][jb + 2 * q];
            fma2(ah0, q0.x, wh[2 * q]); fma2(ah0, q0.y, wh[2 * q + 1]);
            fma2(ah1, q1.x, wh[2 * q]); fma2(ah1, q1.y, wh[2 * q + 1]);
        }
        sredC[0][p][c] = ah0; sredC[1][p][c] = ah1;
        __syncthreads();   // BAR3

        // ---- owner epilogue 2: tanh, h-update, store, publish gamma(t+1)*h ----
        if (owner) {
            float hsx = 0.f, hsy = 0.f;
            #pragma unroll
            for (int k = 0; k < 4; k++) {
                ulonglong2 vh = *(const ulonglong2*)&sredC[b][p][2 * k];
                float2 a0 = up2(vh.x), a1 = up2(vh.y);
                hsx += a0.x + a1.x; hsy += a0.y + a1.y;
            }
            const float* pp = &spre[par][b * 512];
            float2 hp = *(const float2*)&pp[384 + 2 * p];
            float hx = tanhf_(hp.x + hsx), hy = tanhf_(hp.y + hsy);
            float2 hv = up2(h2);
            float h0n = (1.f - zx) * hv.x + zx * hx;
            float h1n = (1.f - zy) * hv.y + zy * hy;
            *(float2*)&hs[((size_t)bg * 1000 + t) * 128 + 2 * p] = make_float2(h0n, h1n);
            float2 gg = *(const float2*)&spre[parn][b * 512 + 2 * p];  // gamma(t+1)
            float s0 = gg.x * h0n, s1 = gg.y * h1n;
            h2 = pk2(s0, s1);
            *(float4*)&shd[b][2 * p] = make_float4(s0, s0, s1, s1);
        }
        __syncthreads();   // BAR4
    }
}

// ============================================================================
// K4: y = sigmoid(hs @ W_hy + b_hy). Packed fma2 over t-pairs.
// ============================================================================
__global__ void __launch_bounds__(256) k4_out(
    const float* __restrict__ hs, const float* __restrict__ Why,
    const float* __restrict__ bhy, float* __restrict__ ys)
{
    extern __shared__ float sm_[];
    float* sh = sm_;               // 128 x 68 (t fast)
    float* sW = sh + 128 * 68;     // 128 x 64
    const int t0 = blockIdx.x * 64, b = blockIdx.y;
    const int tid = threadIdx.x;

    for (int e = tid; e < 8192; e += 256) sW[e] = Why[e];
    for (int e = tid; e < 8192; e += 256) {
        int u = e >> 7, h = e & 127;
        int t = t0 + u;
        sh[h * 68 + u] = (t < 1000) ? hs[((size_t)b * 1000 + t) * 128 + h] : 0.f;
    }
    __syncthreads();

    const int o = tid & 63, q = tid >> 6;
    const int base = q * 16;
    ull acc[8];
    #pragma unroll
    for (int j = 0; j < 8; j++) acc[j] = 0ull;

    for (int h = 0; h < 128; h++) {
        float wv = sW[h * 64 + o];
        ull w2 = pk2(wv, wv);
        const ulonglong2* row = (const ulonglong2*)(sh + h * 68 + base);
        #pragma unroll
        for (int j = 0; j < 4; j++) {
            ulonglong2 v = row[j];
            fma2(acc[2 * j],     v.x, w2);
            fma2(acc[2 * j + 1], v.y, w2);
        }
    }
    float bb = bhy[o];
    #pragma unroll
    for (int j = 0; j < 8; j++) {
        float2 a = up2(acc[j]);
        int t = t0 + base + 2 * j;
        if (t < 1000)     ys[((size_t)b * 1000 + t) * 64 + o]     = sigf(a.x + bb);
        if (t + 1 < 1000) ys[((size_t)b * 1000 + t + 1) * 64 + o] = sigf(a.y + bb);
    }
}

// ============================================================================
extern "C" void kernel_launch(void* const* d_in, const int* in_sizes, int n_in,
                              void* d_out, int out_size)
{
    const float* inp   = (const float*)d_in[0];
    const float* xmean = (const float*)d_in[1];
    const float* Wdgx  = (const float*)d_in[2];
    const float* bdgx  = (const float*)d_in[3];
    const float* Wdgh  = (const float*)d_in[4];
    const float* bdgh  = (const float*)d_in[5];
    const float* Wxz   = (const float*)d_in[6];
    const float* Whz   = (const float*)d_in[7];
    const float* Wmz   = (const float*)d_in[8];
    const float* bmz   = (const float*)d_in[9];
    const float* Wxr   = (const float*)d_in[10];
    const float* Whr   = (const float*)d_in[11];
    const float* Wmr   = (const float*)d_in[12];
    const float* Wxh   = (const float*)d_in[13];
    const float* Whh   = (const float*)d_in[14];
    const float* Wmh   = (const float*)d_in[15];
    const float* bmh   = (const float*)d_in[16];
    const float* Why   = (const float*)d_in[17];
    const float* bhy   = (const float*)d_in[18];

    float* ys = (float*)d_out;                        // (B,T,64)
    float* hs = ys + (size_t)256 * 1000 * 64;         // (B,T,128)

    const int K1_SMEM = (4 * 64 * 129 + 64 * 64) * 4;     // 148480 B
    const int K2_SMEM = (3 * 4096 + 8192) * 4;            // 81920 B
    const int K4_SMEM = (128 * 68 + 8192) * 4;            // 67584 B
    cudaFuncSetAttribute(k1_impute, cudaFuncAttributeMaxDynamicSharedMemorySize, K1_SMEM);
    cudaFuncSetAttribute(k2_pre,    cudaFuncAttributeMaxDynamicSharedMemorySize, K2_SMEM);
    cudaFuncSetAttribute(k4_out,    cudaFuncAttributeMaxDynamicSharedMemorySize, K4_SMEM);

    k1_impute<<<256, 256, K1_SMEM>>>(inp, xmean, Wdgx, bdgx);

    dim3 g2(16, 256);
    k2_pre<<<g2, 256, K2_SMEM>>>(inp, Wdgh, bdgh, Wxz, Wmz, bmz, Wxr, Wmr, Wxh, Wmh, bmh);

    k3_rec<<<128, 512>>>(Whz, Whr, Whh, hs);

    dim3 g4(16, 256);
    k4_out<<<g4, 256, K4_SMEM>>>(hs, Why, bhy, ys);
}

// round 13
// speedup vs baseline: 3.3984x; 3.3984x over previous
#include <cuda_runtime.h>
#include <cuda_bf16.h>
#include <cstdint>

// Problem constants: B=256, IN=64, HID=128, OUT=64, T=1000
// Output: ys (B,T,64) then hs (B,T,128), float32.

typedef unsigned long long ull;

// ------------------------- device scratch (no allocs allowed) --------------
__device__ float g_ximp[256 * 64 * 1000];                 // imputed x (B,IN,T)
__device__ float g_pre[131072000];                        // (B,T,[gamH,preZ,preR,preH],128)

// ------------------------- helpers -----------------------------------------
__device__ __forceinline__ void fma2(ull& d, ull a, ull b) {
    asm("fma.rn.f32x2 %0, %1, %2, %0;" : "+l"(d) : "l"(a), "l"(b));
}
__device__ __forceinline__ ull pk2(float lo, float hi) {
    ull r;
    asm("mov.b64 %0, {%1, %2};" : "=l"(r) : "f"(lo), "f"(hi));
    return r;
}
__device__ __forceinline__ float2 up2(ull v) {
    float2 r;
    asm("mov.b64 {%0, %1}, %2;" : "=f"(r.x), "=f"(r.y) : "l"(v));
    return r;
}
__device__ __forceinline__ float sigf(float x) { return 1.f / (1.f + __expf(-x)); }
__device__ __forceinline__ float tanhf_(float x) { return 1.f - 2.f / (1.f + __expf(2.f * x)); }

// ============================================================================
// K1: imputation. One CTA per batch. gamma_x GEMM + LOCF scan + impute.
// (identical to R10)
// ============================================================================
__global__ void __launch_bounds__(256) k1_impute(
    const float* __restrict__ inp, const float* __restrict__ xmean,
    const float* __restrict__ Wdgx, const float* __restrict__ bdgx)
{
    extern __shared__ float sm_[];
    float* sx  = sm_;                 // 64 x 129
    float* smk = sx + 64 * 129;
    float* sd  = smk + 64 * 129;
    float* sg  = sd + 64 * 129;
    float* sW  = sg + 64 * 129;       // 64 x 64
    const int b = blockIdx.x, tid = threadIdx.x;

    for (int e = tid; e < 64 * 64; e += 256) sW[e] = Wdgx[e];
    float xl  = 0.f;
    float xmn = (tid < 64) ? xmean[tid] : 0.f;

    for (int t0 = 0; t0 < 1000; t0 += 128) {
        const int nv = min(128, 1000 - t0);
        __syncthreads();
        for (int e = tid; e < 64 * 128; e += 256) {
            int i = e >> 7, u = e & 127;
            float xv = 0.f, mv = 0.f, dv = 0.f;
            if (u < nv) {
                size_t gb = ((size_t)(b * 3 * 64) + i) * 1000 + t0 + u;
                xv = inp[gb];
                mv = inp[gb + 64 * 1000];
                dv = inp[gb + 2 * 64 * 1000];
            }
            sx[i * 129 + u] = xv; smk[i * 129 + u] = mv; sd[i * 129 + u] = dv;
        }
        __syncthreads();
        for (int e = tid; e < 64 * 128; e += 256) {
            int j = e >> 7, u = e & 127;
            float acc = bdgx[j];
            #pragma unroll 8
            for (int k = 0; k < 64; k++) acc += sd[k * 129 + u] * sW[k * 64 + j];
            sg[j * 129 + u] = __expf(-fmaxf(acc, 0.f));
        }
        __syncthreads();
        if (tid < 64) {
            const int i = tid;
            for (int u = 0; u < nv; u++) {
                float mv = smk[i * 129 + u], xv = sx[i * 129 + u], gv = sg[i * 129 + u];
                if (mv > 0.f) xl = xv;
                sx[i * 129 + u] = mv * xv + (1.f - mv) * (gv * xl + (1.f - gv) * xmn);
            }
        }
        __syncthreads();
        for (int e = tid; e < 64 * 128; e += 256) {
            int i = e >> 7, u = e & 127;
            if (u < nv) g_ximp[((size_t)(b * 64) + i) * 1000 + t0 + u] = sx[i * 129 + u];
        }
    }
}

// ============================================================================
// K2: pre-activations. CTA = (t-tile 64, batch). f32x2 packed over t-pairs.
// (identical to R10)
// ============================================================================
__device__ __forceinline__ void gemm64(const float* __restrict__ s,
                                       const float* __restrict__ sW,
                                       ull acc[16], int h, int base)
{
    #pragma unroll 4
    for (int k = 0; k < 64; k++) {
        float w = sW[k * 128 + h];
        ull w2 = pk2(w, w);
        const ulonglong2* row = (const ulonglong2*)(s + k * 64 + base);
        #pragma unroll
        for (int j = 0; j < 8; j++) {
            ulonglong2 v = row[j];
            fma2(acc[2 * j],     v.x, w2);
            fma2(acc[2 * j + 1], v.y, w2);
        }
    }
}

__device__ __forceinline__ void store_pre(const ull acc[16],
                                          int b, int t0, int base, int h, int c, float bias)
{
    #pragma unroll
    for (int j = 0; j < 16; j++) {
        float2 a = up2(acc[j]);
        int u = base + 2 * j;
        size_t adr = ((size_t)b * 1000 + t0 + u) * 512 + c * 128 + h;
        if (t0 + u < 1000)     g_pre[adr]       = a.x + bias;
        if (t0 + u + 1 < 1000) g_pre[adr + 512] = a.y + bias;
    }
}

__global__ void __launch_bounds__(256) k2_pre(
    const float* __restrict__ inp,
    const float* __restrict__ Wdgh, const float* __restrict__ bdgh,
    const float* __restrict__ Wxz,  const float* __restrict__ Wmz, const float* __restrict__ bmz,
    const float* __restrict__ Wxr,  const float* __restrict__ Wmr,
    const float* __restrict__ Wxh,  const float* __restrict__ Wmh, const float* __restrict__ bmh)
{
    extern __shared__ float sm_[];
    float* sx  = sm_;          // 64k x 64t
    float* sm2 = sx + 4096;
    float* sd  = sm2 + 4096;
    float* sW  = sd + 4096;    // 64 x 128
    const int t0 = blockIdx.x * 64, b = blockIdx.y;
    const int tid = threadIdx.x, h = tid & 127, base = (tid >> 7) * 32;

    for (int e = tid; e < 4096; e += 256) {
        int k = e >> 6, u = e & 63;
        int t = t0 + u;
        float xv = 0.f, mv = 0.f, dv = 0.f;
        if (t < 1000) {
            xv = g_ximp[((size_t)(b * 64) + k) * 1000 + t];
            size_t gb = ((size_t)(b * 3 * 64) + k) * 1000 + t;
            mv = inp[gb + 64 * 1000];
            dv = inp[gb + 2 * 64 * 1000];
        }
        sx[k * 64 + u] = xv; sm2[k * 64 + u] = mv; sd[k * 64 + u] = dv;
    }
    ull acc[16];

    // ---- c0: gammaH ----
    for (int e = tid; e < 8192; e += 256) sW[e] = Wdgh[e];
    __syncthreads();
    #pragma unroll
    for (int j = 0; j < 16; j++) acc[j] = 0ull;
    gemm64(sd, sW, acc, h, base);
    {
        float bb = bdgh[h];
        #pragma unroll
        for (int j = 0; j < 16; j++) {
            float2 a = up2(acc[j]);
            int u = base + 2 * j;
            size_t adr = ((size_t)b * 1000 + t0 + u) * 512 + h;
            if (t0 + u < 1000)     g_pre[adr]       = __expf(-fmaxf(a.x + bb, 0.f));
            if (t0 + u + 1 < 1000) g_pre[adr + 512] = __expf(-fmaxf(a.y + bb, 0.f));
        }
    }
    // ---- c1: preZ ----
    __syncthreads();
    for (int e = tid; e < 8192; e += 256) sW[e] = Wxz[e];
    __syncthreads();
    #pragma unroll
    for (int j = 0; j < 16; j++) acc[j] = 0ull;
    gemm64(sx, sW, acc, h, base);
    __syncthreads();
    for (int e = tid; e < 8192; e += 256) sW[e] = Wmz[e];
    __syncthreads();
    gemm64(sm2, sW, acc, h, base);
    store_pre(acc, b, t0, base, h, 1, bmz[h]);

    // ---- c2: preR ----
    __syncthreads();
    for (int e = tid; e < 8192; e += 256) sW[e] = Wxr[e];
    __syncthreads();
    #pragma unroll
    for (int j = 0; j < 16; j++) acc[j] = 0ull;
    gemm64(sx, sW, acc, h, base);
    __syncthreads();
    for (int e = tid; e < 8192; e += 256) sW[e] = Wmr[e];
    __syncthreads();
    gemm64(sm2, sW, acc, h, base);
    store_pre(acc, b, t0, base, h, 2, 0.f);

    // ---- c3: preH ----
    __syncthreads();
    for (int e = tid; e < 8192; e += 256) sW[e] = Wxh[e];
    __syncthreads();
    #pragma unroll
    for (int j = 0; j < 16; j++) acc[j] = 0ull;
    gemm64(sx, sW, acc, h, base);
    __syncthreads();
    for (int e = tid; e < 8192; e += 256) sW[e] = Wmh[e];
    __syncthreads();
    gemm64(sm2, sW, acc, h, base);
    store_pre(acc, b, t0, base, h, 3, bmh[h]);
}

// ============================================================================
// K3 v4: R10 structure (256 thr, 192 weight regs, smem reductions, 4 BAR)
// + LDS.128 stage loads + cooperative double-buffered smem prefetch of pre.
// Thread (tid): pair p = tid&63, chunk jg = tid>>6 (32 j each).
// Owners: tid<128 (jg in {0,1}), batch = jg.
// ============================================================================
__global__ void __launch_bounds__(256, 1) k3_rec(
    const float* __restrict__ Whz, const float* __restrict__ Whr,
    const float* __restrict__ Whh, float* __restrict__ hs)
{
    __shared__ ull shd[2][128];       // gamma-scaled h, duplicated pairs, per batch
    __shared__ ull srhd[2][128];      // r*h, duplicated pairs
    __shared__ ull sred[4][256];      // partial sums
    __shared__ float spre[2][1024];   // double-buffered pre-activations (2 batches x 512)

    const int tid = threadIdx.x;
    const int p = tid & 63, jg = tid >> 6;
    const int jb = jg * 32;
    const int bg0 = blockIdx.x * 2;

    // weight slice: 32 j x 3 gates, packed column pairs (W[j][2p], W[j][2p+1])
    ull wz[32], wr[32], wh[32];
    #pragma unroll
    for (int j = 0; j < 32; j++) {
        int row = (jb + j) * 128 + 2 * p;
        wz[j] = *(const ull*)(Whz + row);
        wr[j] = *(const ull*)(Whr + row);
        wh[j] = *(const ull*)(Whh + row);
    }

    // init h = 0
    ((ull*)shd)[tid] = 0ull;

    // cooperative prefetch lanes: each thread owns 4 consecutive floats
    const int pb   = tid >> 7;          // batch 0/1
    const int poff = (tid & 127) * 4;   // float offset within 512

    // preload pre(0) into spre[0]
    {
        float4 v = *(const float4*)&g_pre[((size_t)(bg0 + pb) * 1000) * 512 + poff];
        *(float4*)&spre[0][pb * 512 + poff] = v;
    }

    const bool owner = (tid < 128);
    const int b  = jg;                  // owner's batch (valid when owner)
    const int bg = bg0 + b;

    ull h2 = 0ull;                      // gamma-scaled h pair (owner)
    float zx = 0.f, zy = 0.f;
    __syncthreads();

    for (int t = 0; t < 1000; t++) {
        const int par  = t & 1;
        const int parn = par ^ 1;

        // issue prefetch of pre(t+1); STS deferred to after stage B
        int tn = (t + 1 < 1000) ? t + 1 : 999;
        float4 pf = *(const float4*)&g_pre[((size_t)(bg0 + pb) * 1000 + tn) * 512 + poff];

        // ---- stage B: z/r partial dots (LDS.128 broadcast reads) ----
        ull az0 = 0, az1 = 0, ar0 = 0, ar1 = 0;
        #pragma unroll
        for (int q = 0; q < 16; q++) {
            ulonglong2 h0 = *(const ulonglong2*)&shd[0][jb + 2 * q];
            ulonglong2 h1 = *(const ulonglong2*)&shd[1][jb + 2 * q];
            fma2(az0, h0.x, wz[2 * q]); fma2(az0, h0.y, wz[2 * q + 1]);
            fma2(ar0, h0.x, wr[2 * q]); fma2(ar0, h0.y, wr[2 * q + 1]);
            fma2(az1, h1.x, wz[2 * q]); fma2(az1, h1.y, wz[2 * q + 1]);
            fma2(ar1, h1.x, wr[2 * q]); fma2(ar1, h1.y, wr[2 * q + 1]);
        }
        // deposit prefetched pre (drained by BAR1)
        *(float4*)&spre[parn][pb * 512 + poff] = pf;
        sred[0][tid] = az0; sred[1][tid] = az1; sred[2][tid] = ar0; sred[3][tid] = ar1;
        __syncthreads();   // BAR1

        // ---- owner epilogue 1: z, r activations; publish r*h ----
        if (owner) {
            float zsx = 0.f, zsy = 0.f, rsx = 0.f, rsy = 0.f;
            #pragma unroll
            for (int g = 0; g < 4; g++) {
                float2 a = up2(sred[b][g * 64 + p]);     zsx += a.x; zsy += a.y;
                float2 c = up2(sred[2 + b][g * 64 + p]); rsx += c.x; rsy += c.y;
            }
            const float* pp = &spre[par][b * 512];
            float2 zp = *(const float2*)&pp[128 + 2 * p];
            float2 rp = *(const float2*)&pp[256 + 2 * p];
            zx = sigf(zp.x + zsx); zy = sigf(zp.y + zsy);
            float rx = sigf(rp.x + rsx), ry = sigf(rp.y + rsy);
            float2 hv = up2(h2);
            float v0 = rx * hv.x, v1 = ry * hv.y;
            *(float4*)&srhd[b][2 * p] = make_float4(v0, v0, v1, v1);
        }
        __syncthreads();   // BAR2

        // ---- stage C: h_tilde partial dots ----
        ull ah0 = 0, ah1 = 0;
        #pragma unroll
        for (int q = 0; q < 16; q++) {
            ulonglong2 q0 = *(const ulonglong2*)&srhd[0][jb + 2 * q];
            ulonglong2 q1 = *(const ulonglong2*)&srhd[1][jb + 2 * q];
            fma2(ah0, q0.x, wh[2 * q]); fma2(ah0, q0.y, wh[2 * q + 1]);
            fma2(ah1, q1.x, wh[2 * q]); fma2(ah1, q1.y, wh[2 * q + 1]);
        }
        sred[0][tid] = ah0; sred[1][tid] = ah1;
        __syncthreads();   // BAR3

        // ---- owner epilogue 2: tanh, h update, store, publish gamma(t+1)*h ----
        if (owner) {
            float hsx = 0.f, hsy = 0.f;
            #pragma unroll
            for (int g = 0; g < 4; g++) {
                float2 a = up2(sred[b][g * 64 + p]); hsx += a.x; hsy += a.y;
            }
            const float* pp = &spre[par][b * 512];
            float2 hp = *(const float2*)&pp[384 + 2 * p];
            float hx = tanhf_(hp.x + hsx), hy = tanhf_(hp.y + hsy);
            float2 hv = up2(h2);
            float h0n = (1.f - zx) * hv.x + zx * hx;
            float h1n = (1.f - zy) * hv.y + zy * hy;
            *(float2*)&hs[((size_t)bg * 1000 + t) * 128 + 2 * p] = make_float2(h0n, h1n);
            float2 gg = *(const float2*)&spre[parn][b * 512 + 2 * p];  // gamma(t+1)
            float s0 = gg.x * h0n, s1 = gg.y * h1n;
            h2 = pk2(s0, s1);
            *(float4*)&shd[b][2 * p] = make_float4(s0, s0, s1, s1);
        }
        __syncthreads();   // BAR4
    }
}

// ============================================================================
// K4: y = sigmoid(hs @ W_hy + b_hy). Packed fma2 over t-pairs. (identical R10/11)
// ============================================================================
__global__ void __launch_bounds__(256) k4_out(
    const float* __restrict__ hs, const float* __restrict__ Why,
    const float* __restrict__ bhy, float* __restrict__ ys)
{
    extern __shared__ float sm_[];
    float* sh = sm_;               // 128 x 68 (t fast)
    float* sW = sh + 128 * 68;     // 128 x 64
    const int t0 = blockIdx.x * 64, b = blockIdx.y;
    const int tid = threadIdx.x;

    for (int e = tid; e < 8192; e += 256) sW[e] = Why[e];
    for (int e = tid; e < 8192; e += 256) {
        int u = e >> 7, h = e & 127;
        int t = t0 + u;
        sh[h * 68 + u] = (t < 1000) ? hs[((size_t)b * 1000 + t) * 128 + h] : 0.f;
    }
    __syncthreads();

    const int o = tid & 63, q = tid >> 6;
    const int base = q * 16;
    ull acc[8];
    #pragma unroll
    for (int j = 0; j < 8; j++) acc[j] = 0ull;

    for (int h = 0; h < 128; h++) {
        float wv = sW[h * 64 + o];
        ull w2 = pk2(wv, wv);
        const ulonglong2* row = (const ulonglong2*)(sh + h * 68 + base);
        #pragma unroll
        for (int j = 0; j < 4; j++) {
            ulonglong2 v = row[j];
            fma2(acc[2 * j],     v.x, w2);
            fma2(acc[2 * j + 1], v.y, w2);
        }
    }
    float bb = bhy[o];
    #pragma unroll
    for (int j = 0; j < 8; j++) {
        float2 a = up2(acc[j]);
        int t = t0 + base + 2 * j;
        if (t < 1000)     ys[((size_t)b * 1000 + t) * 64 + o]     = sigf(a.x + bb);
        if (t + 1 < 1000) ys[((size_t)b * 1000 + t + 1) * 64 + o] = sigf(a.y + bb);
    }
}

// ============================================================================
extern "C" void kernel_launch(void* const* d_in, const int* in_sizes, int n_in,
                              void* d_out, int out_size)
{
    const float* inp   = (const float*)d_in[0];
    const float* xmean = (const float*)d_in[1];
    const float* Wdgx  = (const float*)d_in[2];
    const float* bdgx  = (const float*)d_in[3];
    const float* Wdgh  = (const float*)d_in[4];
    const float* bdgh  = (const float*)d_in[5];
    const float* Wxz   = (const float*)d_in[6];
    const float* Whz   = (const float*)d_in[7];
    const float* Wmz   = (const float*)d_in[8];
    const float* bmz   = (const float*)d_in[9];
    const float* Wxr   = (const float*)d_in[10];
    const float* Whr   = (const float*)d_in[11];
    const float* Wmr   = (const float*)d_in[12];
    const float* Wxh   = (const float*)d_in[13];
    const float* Whh   = (const float*)d_in[14];
    const float* Wmh   = (const float*)d_in[15];
    const float* bmh   = (const float*)d_in[16];
    const float* Why   = (const float*)d_in[17];
    const float* bhy   = (const float*)d_in[18];

    float* ys = (float*)d_out;                        // (B,T,64)
    float* hs = ys + (size_t)256 * 1000 * 64;         // (B,T,128)

    const int K1_SMEM = (4 * 64 * 129 + 64 * 64) * 4;     // 148480 B
    const int K2_SMEM = (3 * 4096 + 8192) * 4;            // 81920 B
    const int K4_SMEM = (128 * 68 + 8192) * 4;            // 67584 B
    cudaFuncSetAttribute(k1_impute, cudaFuncAttributeMaxDynamicSharedMemorySize, K1_SMEM);
    cudaFuncSetAttribute(k2_pre,    cudaFuncAttributeMaxDynamicSharedMemorySize, K2_SMEM);
    cudaFuncSetAttribute(k4_out,    cudaFuncAttributeMaxDynamicSharedMemorySize, K4_SMEM);

    k1_impute<<<256, 256, K1_SMEM>>>(inp, xmean, Wdgx, bdgx);

    dim3 g2(16, 256);
    k2_pre<<<g2, 256, K2_SMEM>>>(inp, Wdgh, bdgh, Wxz, Wmz, bmz, Wxr, Wmr, Wxh, Wmh, bmh);

    k3_rec<<<128, 256>>>(Whz, Whr, Whh, hs);

    dim3 g4(16, 256);
    k4_out<<<g4, 256, K4_SMEM>>>(hs, Why, bhy, ys);
}

// round 14
// speedup vs baseline: 3.9148x; 1.1520x over previous
#include <cuda_runtime.h>
#include <cuda_bf16.h>
#include <cstdint>

// Problem constants: B=256, IN=64, HID=128, OUT=64, T=1000
// Output: ys (B,T,64) then hs (B,T,128), float32.

typedef unsigned long long ull;

// ------------------------- device scratch (no allocs allowed) --------------
__device__ float g_ximp[256 * 64 * 1000];                 // imputed x (B,IN,T)
__device__ float g_pre[131072000];                        // (B,T,[gamH,preZ,preR,preH],128)

// ------------------------- helpers -----------------------------------------
__device__ __forceinline__ void fma2(ull& d, ull a, ull b) {
    asm("fma.rn.f32x2 %0, %1, %2, %0;" : "+l"(d) : "l"(a), "l"(b));
}
__device__ __forceinline__ ull pk2(float lo, float hi) {
    ull r;
    asm("mov.b64 %0, {%1, %2};" : "=l"(r) : "f"(lo), "f"(hi));
    return r;
}
__device__ __forceinline__ float2 up2(ull v) {
    float2 r;
    asm("mov.b64 {%0, %1}, %2;" : "=f"(r.x), "=f"(r.y) : "l"(v));
    return r;
}
__device__ __forceinline__ float sigf(float x) { return 1.f / (1.f + __expf(-x)); }
__device__ __forceinline__ float tanhf_(float x) { return 1.f - 2.f / (1.f + __expf(2.f * x)); }

// ============================================================================
// K1: imputation. One CTA per batch. gamma_x GEMM + LOCF scan + impute.
// (identical to R10)
// ============================================================================
__global__ void __launch_bounds__(256) k1_impute(
    const float* __restrict__ inp, const float* __restrict__ xmean,
    const float* __restrict__ Wdgx, const float* __restrict__ bdgx)
{
    extern __shared__ float sm_[];
    float* sx  = sm_;                 // 64 x 129
    float* smk = sx + 64 * 129;
    float* sd  = smk + 64 * 129;
    float* sg  = sd + 64 * 129;
    float* sW  = sg + 64 * 129;       // 64 x 64
    const int b = blockIdx.x, tid = threadIdx.x;

    for (int e = tid; e < 64 * 64; e += 256) sW[e] = Wdgx[e];
    float xl  = 0.f;
    float xmn = (tid < 64) ? xmean[tid] : 0.f;

    for (int t0 = 0; t0 < 1000; t0 += 128) {
        const int nv = min(128, 1000 - t0);
        __syncthreads();
        for (int e = tid; e < 64 * 128; e += 256) {
            int i = e >> 7, u = e & 127;
            float xv = 0.f, mv = 0.f, dv = 0.f;
            if (u < nv) {
                size_t gb = ((size_t)(b * 3 * 64) + i) * 1000 + t0 + u;
                xv = inp[gb];
                mv = inp[gb + 64 * 1000];
                dv = inp[gb + 2 * 64 * 1000];
            }
            sx[i * 129 + u] = xv; smk[i * 129 + u] = mv; sd[i * 129 + u] = dv;
        }
        __syncthreads();
        for (int e = tid; e < 64 * 128; e += 256) {
            int j = e >> 7, u = e & 127;
            float acc = bdgx[j];
            #pragma unroll 8
            for (int k = 0; k < 64; k++) acc += sd[k * 129 + u] * sW[k * 64 + j];
            sg[j * 129 + u] = __expf(-fmaxf(acc, 0.f));
        }
        __syncthreads();
        if (tid < 64) {
            const int i = tid;
            for (int u = 0; u < nv; u++) {
                float mv = smk[i * 129 + u], xv = sx[i * 129 + u], gv = sg[i * 129 + u];
                if (mv > 0.f) xl = xv;
                sx[i * 129 + u] = mv * xv + (1.f - mv) * (gv * xl + (1.f - gv) * xmn);
            }
        }
        __syncthreads();
        for (int e = tid; e < 64 * 128; e += 256) {
            int i = e >> 7, u = e & 127;
            if (u < nv) g_ximp[((size_t)(b * 64) + i) * 1000 + t0 + u] = sx[i * 129 + u];
        }
    }
}

// ============================================================================
// K2 v2: pre-activations with gate-paired weight staging.
// CTA = (t-tile 64, batch). 112KB smem -> 2 CTAs/SM. x/m tiles reused across
// gates; z,r computed in one fused pass (32 packed accumulators).
// ============================================================================
__device__ __forceinline__ void gemm_dual(const float* __restrict__ s,
                                          const float* __restrict__ sWa,
                                          const float* __restrict__ sWb,
                                          ull accA[16], ull accB[16],
                                          int h, int base)
{
    #pragma unroll 2
    for (int k = 0; k < 64; k++) {
        float wa = sWa[k * 128 + h];
        float wb = sWb[k * 128 + h];
        ull wa2 = pk2(wa, wa);
        ull wb2 = pk2(wb, wb);
        const ulonglong2* row = (const ulonglong2*)(s + k * 64 + base);
        #pragma unroll
        for (int j = 0; j < 8; j++) {
            ulonglong2 v = row[j];
            fma2(accA[2 * j],     v.x, wa2);
            fma2(accA[2 * j + 1], v.y, wa2);
            fma2(accB[2 * j],     v.x, wb2);
            fma2(accB[2 * j + 1], v.y, wb2);
        }
    }
}

__device__ __forceinline__ void gemm_one(const float* __restrict__ s,
                                         const float* __restrict__ sW,
                                         ull acc[16], int h, int base)
{
    #pragma unroll 4
    for (int k = 0; k < 64; k++) {
        float w = sW[k * 128 + h];
        ull w2 = pk2(w, w);
        const ulonglong2* row = (const ulonglong2*)(s + k * 64 + base);
        #pragma unroll
        for (int j = 0; j < 8; j++) {
            ulonglong2 v = row[j];
            fma2(acc[2 * j],     v.x, w2);
            fma2(acc[2 * j + 1], v.y, w2);
        }
    }
}

__device__ __forceinline__ void store_pre(const ull acc[16],
                                          int b, int t0, int base, int h, int c, float bias)
{
    #pragma unroll
    for (int j = 0; j < 16; j++) {
        float2 a = up2(acc[j]);
        int u = base + 2 * j;
        size_t adr = ((size_t)b * 1000 + t0 + u) * 512 + c * 128 + h;
        if (t0 + u < 1000)     g_pre[adr]       = a.x + bias;
        if (t0 + u + 1 < 1000) g_pre[adr + 512] = a.y + bias;
    }
}

__global__ void __launch_bounds__(256) k2_pre(
    const float* __restrict__ inp,
    const float* __restrict__ Wdgh, const float* __restrict__ bdgh,
    const float* __restrict__ Wxz,  const float* __restrict__ Wmz, const float* __restrict__ bmz,
    const float* __restrict__ Wxr,  const float* __restrict__ Wmr,
    const float* __restrict__ Wxh,  const float* __restrict__ Wmh, const float* __restrict__ bmh)
{
    extern __shared__ float sm_[];
    float* sx  = sm_;           // 64k x 64t
    float* sm2 = sx + 4096;
    float* sd  = sm2 + 4096;
    float* sWa = sd + 4096;     // 64 x 128
    float* sWb = sWa + 8192;    // 64 x 128
    const int t0 = blockIdx.x * 64, b = blockIdx.y;
    const int tid = threadIdx.x, h = tid & 127, base = (tid >> 7) * 32;

    // load data tiles
    for (int e = tid; e < 4096; e += 256) {
        int k = e >> 6, u = e & 63;
        int t = t0 + u;
        float xv = 0.f, mv = 0.f, dv = 0.f;
        if (t < 1000) {
            xv = g_ximp[((size_t)(b * 64) + k) * 1000 + t];
            size_t gb = ((size_t)(b * 3 * 64) + k) * 1000 + t;
            mv = inp[gb + 64 * 1000];
            dv = inp[gb + 2 * 64 * 1000];
        }
        sx[k * 64 + u] = xv; sm2[k * 64 + u] = mv; sd[k * 64 + u] = dv;
    }

    // ---- pass ZR over x ----
    for (int e = tid; e < 8192; e += 256) { sWa[e] = Wxz[e]; sWb[e] = Wxr[e]; }
    __syncthreads();

    ull accZ[16], accR[16];
    #pragma unroll
    for (int j = 0; j < 16; j++) { accZ[j] = 0ull; accR[j] = 0ull; }
    gemm_dual(sx, sWa, sWb, accZ, accR, h, base);
    __syncthreads();

    // ---- pass ZR over m ----
    for (int e = tid; e < 8192; e += 256) { sWa[e] = Wmz[e]; sWb[e] = Wmr[e]; }
    __syncthreads();
    gemm_dual(sm2, sWa, sWb, accZ, accR, h, base);
    store_pre(accZ, b, t0, base, h, 1, bmz[h]);
    store_pre(accR, b, t0, base, h, 2, 0.f);
    __syncthreads();

    // ---- pass H: x@Wxh + m@Wmh (both weights resident) ----
    for (int e = tid; e < 8192; e += 256) { sWa[e] = Wxh[e]; sWb[e] = Wmh[e]; }
    __syncthreads();
    ull accH[16];
    #pragma unroll
    for (int j = 0; j < 16; j++) accH[j] = 0ull;
    gemm_one(sx,  sWa, accH, h, base);
    gemm_one(sm2, sWb, accH, h, base);
    store_pre(accH, b, t0, base, h, 3, bmh[h]);
    __syncthreads();

    // ---- pass gamma: d@Wdgh ----
    for (int e = tid; e < 8192; e += 256) sWa[e] = Wdgh[e];
    __syncthreads();
    ull accG[16];
    #pragma unroll
    for (int j = 0; j < 16; j++) accG[j] = 0ull;
    gemm_one(sd, sWa, accG, h, base);
    {
        float bb = bdgh[h];
        #pragma unroll
        for (int j = 0; j < 16; j++) {
            float2 a = up2(accG[j]);
            int u = base + 2 * j;
            size_t adr = ((size_t)b * 1000 + t0 + u) * 512 + h;
            if (t0 + u < 1000)     g_pre[adr]       = __expf(-fmaxf(a.x + bb, 0.f));
            if (t0 + u + 1 < 1000) g_pre[adr + 512] = __expf(-fmaxf(a.y + bb, 0.f));
        }
    }
}

// ============================================================================
// K3 v5: persistent recurrence, R10 skeleton with resource rebalance:
//  - wz, wr in registers (128 regs); Whh in smem (frees 64 regs)
//  - h / r*h reads as LDS.128
//  - epilogues distributed across ALL 256 threads (one h-element each)
//  - per-element scalar LDG prefetch of pre(t+1), consumed after barriers
// Thread compute view: pair p = tid&63, chunk jg = tid>>6 (32 j).
// Thread element view: batch be = tid>>7, element he = tid&127.
// ============================================================================
__global__ void __launch_bounds__(256, 1) k3_rec(
    const float* __restrict__ Whz, const float* __restrict__ Whr,
    const float* __restrict__ Whh, float* __restrict__ hs)
{
    extern __shared__ ull smk3[];
    ull* swh  = smk3;            // 8192: swh[j*64+p] = (Whh[j][2p], Whh[j][2p+1])
    ull* shd0 = swh + 8192;      // 128: gamma-scaled h, duplicated pairs, batch 0
    ull* shd1 = shd0 + 128;      // 128: batch 1
    ull* srh0 = shd1 + 128;      // 128: r*h duplicated, batch 0
    ull* srh1 = srh0 + 128;      // 128: batch 1
    ull* sred = srh1 + 128;      // 4*256 partials [gate/batch][tid]

    const int tid = threadIdx.x;
    const int p = tid & 63, jg = tid >> 6;
    const int jb = jg * 32;
    const int bg0 = blockIdx.x * 2;

    // z/r weight slices in registers
    ull wz[32], wr[32];
    #pragma unroll
    for (int j = 0; j < 32; j++) {
        int row = (jb + j) * 128 + 2 * p;
        wz[j] = *(const ull*)(Whz + row);
        wr[j] = *(const ull*)(Whr + row);
    }
    // Whh staged to smem (packed column pairs)
    for (int e = tid; e < 8192; e += 256) {
        int j = e >> 6, pp = e & 63;
        swh[e] = *(const ull*)(Whh + j * 128 + 2 * pp);
    }
    // init h = 0
    shd0[tid & 127] = 0ull;
    if (tid < 128) shd1[tid] = 0ull; else shd1[tid - 128] = 0ull;  // both batches
    // (each slot written at least once; duplicates harmless)

    // element identity
    const int be = tid >> 7, he = tid & 127;
    const int pe = he >> 1, comp = he & 1;
    const int bge = bg0 + be;
    ull* shdE = be ? shd1 : shd0;
    ull* srhE = be ? srh1 : srh0;

    float hbar = 0.f;      // gamma-scaled h for this element
    float cz, cr, ch;      // current step pre-activations
    {
        size_t adr = ((size_t)bge * 1000) * 512 + he;
        cz = g_pre[adr + 128];
        cr = g_pre[adr + 256];
        ch = g_pre[adr + 384];
    }
    float zv = 0.f;
    __syncthreads();

    for (int t = 0; t < 1000; t++) {
        // prefetch pre(t+1) for this element (consumed after BAR3/loop-end)
        int tn = (t + 1 < 1000) ? t + 1 : 999;
        size_t adr = ((size_t)bge * 1000 + tn) * 512 + he;
        float ng = g_pre[adr];
        float nz = g_pre[adr + 128];
        float nr = g_pre[adr + 256];
        float nh = g_pre[adr + 384];

        // ---- stage B: z/r partial dots (LDS.128 broadcast reads) ----
        ull az0 = 0, az1 = 0, ar0 = 0, ar1 = 0;
        #pragma unroll
        for (int q = 0; q < 16; q++) {
            ulonglong2 h0 = *(const ulonglong2*)&shd0[jb + 2 * q];
            ulonglong2 h1 = *(const ulonglong2*)&shd1[jb + 2 * q];
            fma2(az0, h0.x, wz[2 * q]); fma2(az0, h0.y, wz[2 * q + 1]);
            fma2(ar0, h0.x, wr[2 * q]); fma2(ar0, h0.y, wr[2 * q + 1]);
            fma2(az1, h1.x, wz[2 * q]); fma2(az1, h1.y, wz[2 * q + 1]);
            fma2(ar1, h1.x, wr[2 * q]); fma2(ar1, h1.y, wr[2 * q + 1]);
        }
        sred[0 * 256 + tid] = az0; sred[1 * 256 + tid] = az1;
        sred[2 * 256 + tid] = ar0; sred[3 * 256 + tid] = ar1;
        __syncthreads();   // BAR1

        // ---- epilogue 1 (all 256 threads, element view): z, r, publish r*h ----
        {
            float zs = 0.f, rs = 0.f;
            #pragma unroll
            for (int g = 0; g < 4; g++) {
                zs += ((const float*)&sred[be * 256 + g * 64 + pe])[comp];
                rs += ((const float*)&sred[(2 + be) * 256 + g * 64 + pe])[comp];
            }
            zv = sigf(cz + zs);
            float rv = sigf(cr + rs);
            float rh = rv * hbar;
            srhE[2 * pe + comp] = pk2(rh, rh);
        }
        __syncthreads();   // BAR2

        // ---- stage C: h_tilde partial dots (Whh from smem) ----
        ull ah0 = 0, ah1 = 0;
        #pragma unroll
        for (int q = 0; q < 16; q++) {
            ulonglong2 q0 = *(const ulonglong2*)&srh0[jb + 2 * q];
            ulonglong2 q1 = *(const ulonglong2*)&srh1[jb + 2 * q];
            ull w0 = swh[(jb + 2 * q) * 64 + p];
            ull w1 = swh[(jb + 2 * q + 1) * 64 + p];
            fma2(ah0, q0.x, w0); fma2(ah0, q0.y, w1);
            fma2(ah1, q1.x, w0); fma2(ah1, q1.y, w1);
        }
        sred[0 * 256 + tid] = ah0; sred[1 * 256 + tid] = ah1;
        __syncthreads();   // BAR3

        // ---- epilogue 2: tanh, h update, store, publish gamma(t+1)*h ----
        {
            float hsum = 0.f;
            #pragma unroll
            for (int g = 0; g < 4; g++)
                hsum += ((const float*)&sred[be * 256 + g * 64 + pe])[comp];
            float ht = tanhf_(ch + hsum);
            float hn = (1.f - zv) * hbar + zv * ht;
            hs[((size_t)bge * 1000 + t) * 128 + he] = hn;
            hbar = ng * hn;
            shdE[2 * pe + comp] = pk2(hbar, hbar);
            cz = nz; cr = nr; ch = nh;
        }
        __syncthreads();   // BAR4
    }
}

// ============================================================================
// K4: y = sigmoid(hs @ W_hy + b_hy). Packed fma2 over t-pairs. (identical)
// ============================================================================
__global__ void __launch_bounds__(256) k4_out(
    const float* __restrict__ hs, const float* __restrict__ Why,
    const float* __restrict__ bhy, float* __restrict__ ys)
{
    extern __shared__ float sm_[];
    float* sh = sm_;               // 128 x 68 (t fast)
    float* sW = sh + 128 * 68;     // 128 x 64
    const int t0 = blockIdx.x * 64, b = blockIdx.y;
    const int tid = threadIdx.x;

    for (int e = tid; e < 8192; e += 256) sW[e] = Why[e];
    for (int e = tid; e < 8192; e += 256) {
        int u = e >> 7, h = e & 127;
        int t = t0 + u;
        sh[h * 68 + u] = (t < 1000) ? hs[((size_t)b * 1000 + t) * 128 + h] : 0.f;
    }
    __syncthreads();

    const int o = tid & 63, q = tid >> 6;
    const int base = q * 16;
    ull acc[8];
    #pragma unroll
    for (int j = 0; j < 8; j++) acc[j] = 0ull;

    for (int h = 0; h < 128; h++) {
        float wv = sW[h * 64 + o];
        ull w2 = pk2(wv, wv);
        const ulonglong2* row = (const ulonglong2*)(sh + h * 68 + base);
        #pragma unroll
        for (int j = 0; j < 4; j++) {
            ulonglong2 v = row[j];
            fma2(acc[2 * j],     v.x, w2);
            fma2(acc[2 * j + 1], v.y, w2);
        }
    }
    float bb = bhy[o];
    #pragma unroll
    for (int j = 0; j < 8; j++) {
        float2 a = up2(acc[j]);
        int t = t0 + base + 2 * j;
        if (t < 1000)     ys[((size_t)b * 1000 + t) * 64 + o]     = sigf(a.x + bb);
        if (t + 1 < 1000) ys[((size_t)b * 1000 + t + 1) * 64 + o] = sigf(a.y + bb);
    }
}

// ============================================================================
extern "C" void kernel_launch(void* const* d_in, const int* in_sizes, int n_in,
                              void* d_out, int out_size)
{
    const float* inp   = (const float*)d_in[0];
    const float* xmean = (const float*)d_in[1];
    const float* Wdgx  = (const float*)d_in[2];
    const float* bdgx  = (const float*)d_in[3];
    const float* Wdgh  = (const float*)d_in[4];
    const float* bdgh  = (const float*)d_in[5];
    const float* Wxz   = (const float*)d_in[6];
    const float* Whz   = (const float*)d_in[7];
    const float* Wmz   = (const float*)d_in[8];
    const float* bmz   = (const float*)d_in[9];
    const float* Wxr   = (const float*)d_in[10];
    const float* Whr   = (const float*)d_in[11];
    const float* Wmr   = (const float*)d_in[12];
    const float* Wxh   = (const float*)d_in[13];
    const float* Whh   = (const float*)d_in[14];
    const float* Wmh   = (const float*)d_in[15];
    const float* bmh   = (const float*)d_in[16];
    const float* Why   = (const float*)d_in[17];
    const float* bhy   = (const float*)d_in[18];

    float* ys = (float*)d_out;                        // (B,T,64)
    float* hs = ys + (size_t)256 * 1000 * 64;         // (B,T,128)

    const int K1_SMEM = (4 * 64 * 129 + 64 * 64) * 4;      // 148480 B
    const int K2_SMEM = (3 * 4096 + 2 * 8192) * 4;         // 114688 B
    const int K3_SMEM = (8192 + 4 * 128 + 4 * 256) * 8;    // 77824 B
    const int K4_SMEM = (128 * 68 + 8192) * 4;             // 67584 B
    cudaFuncSetAttribute(k1_impute, cudaFuncAttributeMaxDynamicSharedMemorySize, K1_SMEM);
    cudaFuncSetAttribute(k2_pre,    cudaFuncAttributeMaxDynamicSharedMemorySize, K2_SMEM);
    cudaFuncSetAttribute(k3_rec,    cudaFuncAttributeMaxDynamicSharedMemorySize, K3_SMEM);
    cudaFuncSetAttribute(k4_out,    cudaFuncAttributeMaxDynamicSharedMemorySize, K4_SMEM);

    k1_impute<<<256, 256, K1_SMEM>>>(inp, xmean, Wdgx, bdgx);

    dim3 g2(16, 256);
    k2_pre<<<g2, 256, K2_SMEM>>>(inp, Wdgh, bdgh, Wxz, Wmz, bmz, Wxr, Wmr, Wxh, Wmh, bmh);

    k3_rec<<<128, 256, K3_SMEM>>>(Whz, Whr, Whh, hs);

    dim3 g4(16, 256);
    k4_out<<<g4, 256, K4_SMEM>>>(hs, Why, bhy, ys);
}